// round 8
// baseline (speedup 1.0000x reference)
#include <cuda_runtime.h>
#include <math.h>

// RoIPooling, single kernel, native layout.
// feat [B,C,50,50] f32, rois [N,5] f32, img scalars -> out [N,C,7,7] f32.
// Bench: B=2, C=256, N=128, IMG=800.
//
// Block = (roi, oh): 896 blocks x 256 threads (8 warps).
// Warp  = 32 consecutive channels.
// Lane  = (ow = lane/4, j = lane&3): 4 lanes per output bin; bin width <= 8
//         covered by x = xs+j and x = xs+j+4 (second load predicated).
// Per channel: loop rows (<=8) of predicated coalesced row-segment loads,
// then 2x shfl_xor nibble max, direct store to out. No smem, no scratch.

#define C_DIM 256
#define FH 50
#define FW 50
#define NPIX (FH * FW)
#define OH 7
#define OW 7
#define QD (OH * OW)

__device__ __forceinline__ float decode_dim(const void* p) {
    int v = *reinterpret_cast<const int*>(p);
    if (v > 0 && v < 1000000) return (float)v;   // int scalar (800 = 0x320)
    return __int_as_float(v);                     // float bits
}

__global__ void __launch_bounds__(256)
roipool_kernel(const float* __restrict__ feat,
               const float* __restrict__ rois,
               const void* __restrict__ img_h_p,
               const void* __restrict__ img_w_p,
               float* __restrict__ out) {
    int unit = blockIdx.x;          // n * OH + oh
    int oh = unit % OH;
    int n  = unit / OH;
    int wid  = threadIdx.x >> 5;    // warp 0..7 -> channels wid*32..wid*32+31
    int lane = threadIdx.x & 31;
    int ow = lane >> 2;             // 0..7 (7 = inactive nibble)
    int j  = lane & 3;

    // ---- block-uniform bound math (exact reference rounding) ----
    float img_h = decode_dim(img_h_p);
    float img_w = decode_dim(img_w_p);
    float sh = __fdiv_rn((float)FH, img_h);
    float sw = __fdiv_rn((float)FW, img_w);

    const float* r = rois + n * 5;
    int bidx = (int)r[0];
    // floor(roi * s) with single rn-multiply, then torch-style clamps
    int x1 = max((int)floorf(__fmul_rn(r[1], sw)), 0);
    int y1 = max((int)floorf(__fmul_rn(r[2], sh)), 0);
    int x2 = min((int)floorf(__fmul_rn(r[3], sw)), FW);
    int y2 = min((int)floorf(__fmul_rn(r[4], sh)), FH);

    float bh = __fdiv_rn((float)max(y2 - y1, 1), (float)OH);
    float bw = __fdiv_rn((float)max(x2 - x1, 1), (float)OW);
    float y1f = (float)y1, x1f = (float)x1;

    // mul then add, each correctly rounded (no FMA contraction) — matches jnp
    int ys = (int)floorf(__fadd_rn(y1f, __fmul_rn((float)oh,       bh)));
    int ye = (int)floorf(__fadd_rn(y1f, __fmul_rn((float)(oh + 1), bh)));
    ys = min(max(ys, 0), FH - 1);
    ye = min(max(ye, 0), FH);

    int owc = min(ow, OW - 1);      // lane-safe ow for the math; masked below
    int xs = (int)floorf(__fadd_rn(x1f, __fmul_rn((float)owc,       bw)));
    int xe = (int)floorf(__fadd_rn(x1f, __fmul_rn((float)(owc + 1), bw)));
    xs = min(max(xs, 0), FW - 1);
    xe = min(max(xe, 0), FW);
    if (ow >= OW) { xs = 0; xe = 0; }   // lanes 28..31 idle

    int rows = ye - ys;
    bool valid = (rows > 0) && (xe > xs);

    int x = xs + j;
    bool pr0 = (x     < xe);        // bin width <= 8: two candidate columns
    bool pr1 = (x + 4 < xe);

    const float* base = feat + ((size_t)bidx * C_DIM + wid * 32) * NPIX
                             + (size_t)ys * FW;
    float* outp = out + ((size_t)n * C_DIM + wid * 32) * QD + oh * OW + ow;

    // ---- 32 channels per warp, unrolled x2 for MLP + shared loop control ----
    for (int i = 0; i < 32; i += 2) {
        const float* pa = base + (size_t)i * NPIX;
        const float* pb = pa + NPIX;
        float m0 = -INFINITY, m1 = -INFINITY;
        for (int y = 0; y < rows; ++y) {
            float a0 = pr0 ? __ldg(pa + x)     : -INFINITY;
            float a1 = pr1 ? __ldg(pa + x + 4) : -INFINITY;
            float b0 = pr0 ? __ldg(pb + x)     : -INFINITY;
            float b1 = pr1 ? __ldg(pb + x + 4) : -INFINITY;
            m0 = fmaxf(m0, fmaxf(a0, a1));
            m1 = fmaxf(m1, fmaxf(b0, b1));
            pa += FW; pb += FW;
        }
        // nibble (4-lane) max within the bin
        m0 = fmaxf(m0, __shfl_xor_sync(0xffffffffu, m0, 1));
        m0 = fmaxf(m0, __shfl_xor_sync(0xffffffffu, m0, 2));
        m1 = fmaxf(m1, __shfl_xor_sync(0xffffffffu, m1, 1));
        m1 = fmaxf(m1, __shfl_xor_sync(0xffffffffu, m1, 2));

        if (j == 0 && ow < OW) {
            outp[(size_t)i * QD]       = valid ? m0 : 0.0f;
            outp[(size_t)(i + 1) * QD] = valid ? m1 : 0.0f;
        }
    }
}

extern "C" void kernel_launch(void* const* d_in, const int* in_sizes, int n_in,
                              void* d_out, int out_size) {
    const float* feat = (const float*)d_in[0];
    const float* rois = (const float*)d_in[1];
    const void*  imh  = d_in[2];
    const void*  imw  = d_in[3];
    float* out = (float*)d_out;

    int nrois = in_sizes[1] / 5;
    roipool_kernel<<<nrois * OH, 256>>>(feat, rois, imh, imw, out);
}